// round 11
// baseline (speedup 1.0000x reference)
#include <cuda_runtime.h>
#include <cstddef>
#include <cstdint>

// RoutingByAgreement: x[B,64,64] f32 -> v[B,64] f32, 3 iterations.
// 256-thread persistent CTAs (5/SM), double-buffered cp.async, approx FP.
// Lane mapping: w=t>>5, l=t&31, g=l>>3 (row-group 0..3), dlo=l&7, d=8w+dlo.
//   s-phase:   xB[j]=x[16g+j][d] regs; reduce over g = shfl xor 8,16.
//   agreement: row n'=d, quarter q'=g, from swizzled smem; reduce = xor 8,16.
// Smem buf uses a 16B-chunk XOR swizzle (chunk ^= (row>>4)<<1) so the xB
// column gather is bank-conflict-free despite the 4x g-replication.
// 2 barriers per routing iteration.

#define FULLMASK 0xffffffffu

static __device__ __forceinline__ void cp_async16(void* smem_dst, const void* gsrc) {
    uint32_t s = (uint32_t)__cvta_generic_to_shared(smem_dst);
    asm volatile("cp.async.cg.shared.global [%0], [%1], 16;\n" :: "r"(s), "l"(gsrc));
}
static __device__ __forceinline__ void cp_async_commit() {
    asm volatile("cp.async.commit_group;\n" ::: "memory");
}
template<int N> static __device__ __forceinline__ void cp_async_wait() {
    asm volatile("cp.async.wait_group %0;\n" :: "n"(N) : "memory");
}
static __device__ __forceinline__ float frcp(float x) {
    float r; asm("rcp.approx.f32 %0, %1;" : "=f"(r) : "f"(x)); return r;
}
static __device__ __forceinline__ float frsq(float x) {
    float r; asm("rsqrt.approx.f32 %0, %1;" : "=f"(r) : "f"(x)); return r;
}

__global__ void __launch_bounds__(256, 5)
routing_kernel(const float* __restrict__ x, float* __restrict__ out, int B)
{
    __shared__ __align__(16) float buf[2][4096];  // 32 KB double buffer (swizzled)
    __shared__ __align__(16) float sS[64];        // normalized s vector
    __shared__ __align__(16) float snq[8];        // per-warp |s|^2 partials
    __shared__ __align__(16) float se[64];        // exp(logits), unnormalized

    const int t = threadIdx.x;
    const int w = t >> 5, l = t & 31;
    const int g = l >> 3, dlo = l & 7;
    const int d = w * 8 + dlo;
    const int stride = gridDim.x;

    // prefetch addressing: thread covers row prow = t>>2, chunks 4*pq..4*pq+3
    const int prow = t >> 2, pq = t & 3;
    const int pswz = (prow >> 4) << 1;            // XOR swizzle for stores

    // xB gather: float offset (16g+j)*64 + swizzled_chunk*4 + (d&3)
    const int xb_off = (16 * g) * 64 + (((d >> 2) ^ (g << 1)) << 2) + (d & 3);
    // agreement row: row = d, chunk (4g+i) ^ aswz
    const int aswz = (d >> 4) << 1;

    // prologue: prefetch first batch into buf[0]
    const int b0 = blockIdx.x;
    {
        const float* src = x + (size_t)b0 * 4096 + t * 16;
        float* dstb = &buf[0][prow * 64];
#pragma unroll
        for (int i = 0; i < 4; i++)
            cp_async16(dstb + (((4 * pq + i) ^ pswz) << 2), src + 4 * i);
    }
    cp_async_commit();

    int k = 0;
    for (int b = b0; b < B; b += stride, k ^= 1) {
        const int bn = b + stride;
        if (bn < B) {
            const float* src = x + (size_t)bn * 4096 + t * 16;
            float* dstb = &buf[k ^ 1][prow * 64];
#pragma unroll
            for (int i = 0; i < 4; i++)
                cp_async16(dstb + (((4 * pq + i) ^ pswz) << 2), src + 4 * i);
        }
        cp_async_commit();
        cp_async_wait<1>();            // current batch's group retired
        __syncthreads();               // buf[k] visible; prev batch reads done

        const float* __restrict__ bp = &buf[k][0];
        const float4* __restrict__ ar  = reinterpret_cast<const float4*>(bp + d * 64);
        const float4* __restrict__ sS4 = reinterpret_cast<const float4*>(sS);
        const float4* __restrict__ se4 = reinterpret_cast<const float4*>(se);

        // xB: 16 conflict-free scalar LDS (swizzled base, stride 64 floats)
        float xB[16];
#pragma unroll
        for (int j = 0; j < 16; j++) xB[j] = bp[xb_off + j * 64];

        float blog = 0.0f;             // logit for row n' = d (all replicas)

#pragma unroll
        for (int it = 0; it < 3; it++) {
            // ---- s-phase ----
            float p, zinv;
            if (it == 0) {
                float p0 = 0.f, p1 = 0.f;
#pragma unroll
                for (int j = 0; j < 16; j += 2) { p0 += xB[j]; p1 += xB[j + 1]; }
                p = p0 + p1;
                zinv = 1.0f / 64.0f;   // softmax(0) = 1/64
            } else {
                float zl = se[l] + se[l + 32];
#pragma unroll
                for (int off = 16; off > 0; off >>= 1)
                    zl += __shfl_xor_sync(FULLMASK, zl, off);
                zinv = frcp(zl);
                float q0 = 0.f, q1 = 0.f;
#pragma unroll
                for (int m = 0; m < 4; m++) {
                    float4 e = se4[4 * g + m];   // weights for rows 16g+4m..
                    q0 += e.x * xB[4 * m]     + e.y * xB[4 * m + 1];
                    q1 += e.z * xB[4 * m + 2] + e.w * xB[4 * m + 3];
                }
                p = q0 + q1;
            }
            // reduce over the 4 row-groups: lanes l, l^8, l^16, l^24
            p += __shfl_xor_sync(FULLMASK, p, 8);
            p += __shfl_xor_sync(FULLMASK, p, 16);
            float s = p * zinv;        // full s[d], on all g-replicas

            // warp-partial |s|^2 over its 8 distinct d's
            float nqp = s * s;
            nqp += __shfl_xor_sync(FULLMASK, nqp, 1);
            nqp += __shfl_xor_sync(FULLMASK, nqp, 2);
            nqp += __shfl_xor_sync(FULLMASK, nqp, 4);
            if (l == 0) snq[w] = nqp;
            if (l < 8)  sS[d] = s;
            __syncthreads();           // barrier 1

            float4 n0 = reinterpret_cast<const float4*>(snq)[0];
            float4 n1 = reinterpret_cast<const float4*>(snq)[1];
            float nsq = (n0.x + n0.y + n0.z + n0.w)
                      + (n1.x + n1.y + n1.z + n1.w);
            float rn    = frsq(nsq + 1e-20f);
            float nrm   = nsq * rn;                          // sqrt(nsq)
            float scale = nsq * frcp((1.0f + nsq) * (nrm + 1e-8f));

            if (it == 2) {             // final: write v, no agreement
                if (l < 8) out[(size_t)b * 64 + d] = s * scale;
                break;
            }

            // ---- agreement: a[d] = <x[d], v>, quarter q'=g per thread ----
            float a = 0.0f;
#pragma unroll
            for (int i = 0; i < 4; i++) {
                float4 xr = ar[(4 * g + i) ^ aswz];  // x[d][16g+4i..]
                float4 sv = sS4[4 * g + i];
                a += xr.x * sv.x + xr.y * sv.y + xr.z * sv.z + xr.w * sv.w;
            }
            a += __shfl_xor_sync(FULLMASK, a, 8);
            a += __shfl_xor_sync(FULLMASK, a, 16);
            a *= scale;                // fold squash scale once, post-reduce
            blog += a;
            if (l < 8) se[d] = __expf(blog);   // one writer per row
            __syncthreads();           // barrier 2 (se ready; sS/snq WAR safe)
        }
    }
}

extern "C" void kernel_launch(void* const* d_in, const int* in_sizes, int n_in,
                              void* d_out, int out_size)
{
    const float* x = (const float*)d_in[0];
    float* out = (float*)d_out;
    const int B = in_sizes[0] / 4096;
    int grid = 148 * 5;                // persistent: 5 CTAs per SM
    if (grid > B) grid = B;
    routing_kernel<<<grid, 256>>>(x, out, B);
}

// round 12
// speedup vs baseline: 1.9120x; 1.9120x over previous
#include <cuda_runtime.h>
#include <cstddef>
#include <cstdint>

// RoutingByAgreement: x[B,64,64] f32 -> v[B,64] f32, 3 iterations.
// 256-thread persistent CTAs (5/SM), double-buffered cp.async, approx FP.
// Lane mapping: w=t>>5, l=t&31, g=l>>3 (row-group 0..3), dlo=l&7, d=8w+dlo.
//   s-phase:   xB[j]=x[16g+j][d] regs; reduce over g = shfl xor 8,16.
//   agreement: row n'=d, quarter q'=g, from swizzled smem; reduce = xor 8,16.
// Smem swizzle: x[row][col] stored at chunk (col>>2) ^ fswz(row),
//   fswz(row) = ((row>>4)<<1) ^ (row&7).
// This makes BOTH the column gather (g-replicated) and the row reads
// (dlo-spread) hit all 8 bank groups -> LDS at wavefront floor.
// 2 barriers per routing iteration.

#define FULLMASK 0xffffffffu

static __device__ __forceinline__ void cp_async16(void* smem_dst, const void* gsrc) {
    uint32_t s = (uint32_t)__cvta_generic_to_shared(smem_dst);
    asm volatile("cp.async.cg.shared.global [%0], [%1], 16;\n" :: "r"(s), "l"(gsrc));
}
static __device__ __forceinline__ void cp_async_commit() {
    asm volatile("cp.async.commit_group;\n" ::: "memory");
}
template<int N> static __device__ __forceinline__ void cp_async_wait() {
    asm volatile("cp.async.wait_group %0;\n" :: "n"(N) : "memory");
}
static __device__ __forceinline__ float frcp(float x) {
    float r; asm("rcp.approx.f32 %0, %1;" : "=f"(r) : "f"(x)); return r;
}
static __device__ __forceinline__ float frsq(float x) {
    float r; asm("rsqrt.approx.f32 %0, %1;" : "=f"(r) : "f"(x)); return r;
}

__global__ void __launch_bounds__(256, 5)
routing_kernel(const float* __restrict__ x, float* __restrict__ out, int B)
{
    __shared__ __align__(16) float buf[2][4096];  // 32 KB double buffer (swizzled)
    __shared__ __align__(16) float sS[64];        // normalized s vector
    __shared__ __align__(16) float snq[8];        // per-warp |s|^2 partials
    __shared__ __align__(16) float se[64];        // exp(logits), unnormalized

    const int t = threadIdx.x;
    const int w = t >> 5, l = t & 31;
    const int g = l >> 3, dlo = l & 7;
    const int d = w * 8 + dlo;
    const int stride = gridDim.x;

    // prefetch addressing: thread covers row prow = t>>2, chunks 4*pq..4*pq+3
    const int prow = t >> 2, pq = t & 3;
    const int pfz = ((prow >> 4) << 1) ^ (prow & 7);   // fswz(prow)

    // xB gather: chunk_j = (d>>2) ^ fswz(16g+j) = (d>>2) ^ (g<<1) ^ (j&7)
    const int xbK = (d >> 2) ^ (g << 1);
    // agreement rows: chunk = (4g+i) ^ fswz(d)
    const int afz = ((d >> 4) << 1) ^ (d & 7);

    // prologue: prefetch first batch into buf[0]
    const int b0 = blockIdx.x;
    {
        const float* src = x + (size_t)b0 * 4096 + t * 16;
        float* dstb = &buf[0][prow * 64];
#pragma unroll
        for (int i = 0; i < 4; i++)
            cp_async16(dstb + (((4 * pq + i) ^ pfz) << 2), src + 4 * i);
    }
    cp_async_commit();

    int k = 0;
    for (int b = b0; b < B; b += stride, k ^= 1) {
        const int bn = b + stride;
        if (bn < B) {
            const float* src = x + (size_t)bn * 4096 + t * 16;
            float* dstb = &buf[k ^ 1][prow * 64];
#pragma unroll
            for (int i = 0; i < 4; i++)
                cp_async16(dstb + (((4 * pq + i) ^ pfz) << 2), src + 4 * i);
        }
        cp_async_commit();
        cp_async_wait<1>();            // current batch's group retired
        __syncthreads();               // buf[k] visible; prev batch reads done

        const float* __restrict__ bp = &buf[k][0];
        const float4* __restrict__ ar  = reinterpret_cast<const float4*>(bp + d * 64);
        const float4* __restrict__ sS4 = reinterpret_cast<const float4*>(sS);
        const float4* __restrict__ se4 = reinterpret_cast<const float4*>(se);

        // xB: 16 conflict-free scalar LDS (per-j swizzled chunk)
        float xB[16];
        {
            const float* base = bp + g * 1024 + (d & 3);
#pragma unroll
            for (int j = 0; j < 16; j++)
                xB[j] = base[j * 64 + ((xbK ^ (j & 7)) << 2)];
        }

        float blog = 0.0f;             // logit for row n' = d (all replicas)

#pragma unroll
        for (int it = 0; it < 3; it++) {
            // ---- s-phase ----
            float p, zinv;
            if (it == 0) {
                float p0 = 0.f, p1 = 0.f;
#pragma unroll
                for (int j = 0; j < 16; j += 2) { p0 += xB[j]; p1 += xB[j + 1]; }
                p = p0 + p1;
                zinv = 1.0f / 64.0f;   // softmax(0) = 1/64
            } else {
                float zl = se[l] + se[l + 32];
#pragma unroll
                for (int off = 16; off > 0; off >>= 1)
                    zl += __shfl_xor_sync(FULLMASK, zl, off);
                zinv = frcp(zl);
                float q0 = 0.f, q1 = 0.f;
#pragma unroll
                for (int m = 0; m < 4; m++) {
                    float4 e = se4[4 * g + m];   // weights for rows 16g+4m..
                    q0 += e.x * xB[4 * m]     + e.y * xB[4 * m + 1];
                    q1 += e.z * xB[4 * m + 2] + e.w * xB[4 * m + 3];
                }
                p = q0 + q1;
            }
            // reduce over the 4 row-groups: lanes l, l^8, l^16, l^24
            p += __shfl_xor_sync(FULLMASK, p, 8);
            p += __shfl_xor_sync(FULLMASK, p, 16);
            float s = p * zinv;        // full s[d], on all g-replicas

            // warp-partial |s|^2 over its 8 distinct d's
            float nqp = s * s;
            nqp += __shfl_xor_sync(FULLMASK, nqp, 1);
            nqp += __shfl_xor_sync(FULLMASK, nqp, 2);
            nqp += __shfl_xor_sync(FULLMASK, nqp, 4);
            if (l == 0) snq[w] = nqp;
            if (l < 8)  sS[d] = s;
            __syncthreads();           // barrier 1

            float4 n0 = reinterpret_cast<const float4*>(snq)[0];
            float4 n1 = reinterpret_cast<const float4*>(snq)[1];
            float nsq = (n0.x + n0.y + n0.z + n0.w)
                      + (n1.x + n1.y + n1.z + n1.w);
            float rn    = frsq(nsq + 1e-20f);
            float nrm   = nsq * rn;                          // sqrt(nsq)
            float scale = nsq * frcp((1.0f + nsq) * (nrm + 1e-8f));

            if (it == 2) {             // final: write v, no agreement
                if (l < 8) out[(size_t)b * 64 + d] = s * scale;
                break;
            }

            // ---- agreement: a[d] = <x[d], v>, quarter q'=g per thread ----
            float a = 0.0f;
#pragma unroll
            for (int i = 0; i < 4; i++) {
                float4 xr = ar[(4 * g + i) ^ afz];   // x[d][chunk 4g+i]
                float4 sv = sS4[4 * g + i];
                a += xr.x * sv.x + xr.y * sv.y + xr.z * sv.z + xr.w * sv.w;
            }
            a += __shfl_xor_sync(FULLMASK, a, 8);
            a += __shfl_xor_sync(FULLMASK, a, 16);
            a *= scale;                // fold squash scale once, post-reduce
            blog += a;
            if (l < 8) se[d] = __expf(blog);   // one writer per row
            __syncthreads();           // barrier 2 (se ready; sS/snq WAR safe)
        }
    }
}

extern "C" void kernel_launch(void* const* d_in, const int* in_sizes, int n_in,
                              void* d_out, int out_size)
{
    const float* x = (const float*)d_in[0];
    float* out = (float*)d_out;
    const int B = in_sizes[0] / 4096;
    int grid = 148 * 5;                // persistent: 5 CTAs per SM
    if (grid > B) grid = B;
    routing_kernel<<<grid, 256>>>(x, out, B);
}

// round 13
// speedup vs baseline: 4.0069x; 2.0956x over previous
#include <cuda_runtime.h>
#include <cstddef>
#include <cstdint>

// RoutingByAgreement: x[B,64,64] f32 -> v[B,64] f32, 3 iterations.
// ONE WARP PER BATCH, zero __syncthreads. 128-thread CTAs, 3 CTAs/SM
// (12 independent warps = 12 batches in flight per SM).
// Lane l owns columns 2l, 2l+1 of the 64x64 tile: float2 xc[64] in registers.
//   s-phase:   in-lane (no communication).
//   |s|^2, Z:  5-shfl warp reductions.
//   agreement: 5-step butterfly reduce-scatter (rows->lanes), logits in regs.
//   softmax c: per-warp se[64] smem strip, __syncwarp only.
// Next batch prefetched to L2 (prefetch.global.L2) while current computes.

#define FULLMASK 0xffffffffu

static __device__ __forceinline__ float frcp(float x) {
    float r; asm("rcp.approx.f32 %0, %1;" : "=f"(r) : "f"(x)); return r;
}
static __device__ __forceinline__ float frsq(float x) {
    float r; asm("rsqrt.approx.f32 %0, %1;" : "=f"(r) : "f"(x)); return r;
}

__global__ void __launch_bounds__(128, 3)
routing_kernel(const float* __restrict__ x, float* __restrict__ out, int B)
{
    __shared__ __align__(16) float se[4][64];   // per-warp softmax strip

    const int t = threadIdx.x;
    const int wid = t >> 5, l = t & 31;
    float* __restrict__ sew = se[wid];

    const int gwarp = blockIdx.x * 4 + wid;
    const int nwarps = gridDim.x * 4;

    // butterfly reduce-scatter output rows: bit5..bit1 of row <- bit0..bit4 of l
    const int r0 = ((l & 1) << 5) | ((l & 2) << 3) | ((l & 4) << 1)
                 | ((l & 8) >> 1) | ((l & 16) >> 3);        // even; r1 = r0+1

    for (int b = gwarp; b < B; b += nwarps) {
        const float* __restrict__ xb = x + (size_t)b * 4096 + 2 * l;

        // ---- load tile: 64 coalesced LDG.64 per lane ----
        float2 xc[64];
#pragma unroll
        for (int n = 0; n < 64; n++)
            xc[n] = *reinterpret_cast<const float2*>(xb + n * 64);

        // ---- prefetch next batch into L2 (4 x 128B lines per lane) ----
        {
            const int bn = b + nwarps;
            if (bn < B) {
                const char* pf = (const char*)(x + (size_t)bn * 4096) + l * 128;
#pragma unroll
                for (int i = 0; i < 4; i++)
                    asm volatile("prefetch.global.L2 [%0];" :: "l"(pf + i * 4096));
            }
        }

        float blog0 = 0.f, blog1 = 0.f;   // logits for rows r0, r0+1
        float e0 = 0.f, e1 = 0.f;         // own unnormalized exps

#pragma unroll
        for (int it = 0; it < 3; it++) {
            // ---- s-phase (in-lane) ----
            float s0, s1;
            if (it == 0) {
                float a0 = 0.f, a1 = 0.f, c0 = 0.f, c1 = 0.f;
#pragma unroll
                for (int n = 0; n < 64; n += 2) {
                    a0 += xc[n].x;     a1 += xc[n].y;
                    c0 += xc[n + 1].x; c1 += xc[n + 1].y;
                }
                s0 = (a0 + c0) * (1.0f / 64.0f);
                s1 = (a1 + c1) * (1.0f / 64.0f);
            } else {
                float zl = e0 + e1;                    // Z over all 64 rows
#pragma unroll
                for (int off = 16; off > 0; off >>= 1)
                    zl += __shfl_xor_sync(FULLMASK, zl, off);
                const float zinv = frcp(zl);
                float p0 = 0.f, p1 = 0.f, q0 = 0.f, q1 = 0.f;
                const float4* __restrict__ c4 = reinterpret_cast<const float4*>(sew);
#pragma unroll
                for (int m = 0; m < 16; m++) {
                    float4 c = c4[m];                  // broadcast LDS.128
                    p0 = fmaf(c.x, xc[4 * m].x, p0);     p1 = fmaf(c.x, xc[4 * m].y, p1);
                    q0 = fmaf(c.y, xc[4 * m + 1].x, q0); q1 = fmaf(c.y, xc[4 * m + 1].y, q1);
                    p0 = fmaf(c.z, xc[4 * m + 2].x, p0); p1 = fmaf(c.z, xc[4 * m + 2].y, p1);
                    q0 = fmaf(c.w, xc[4 * m + 3].x, q0); q1 = fmaf(c.w, xc[4 * m + 3].y, q1);
                }
                s0 = (p0 + q0) * zinv;
                s1 = (p1 + q1) * zinv;
            }

            // ---- squash scale: nq = |s|^2 via 5-shfl warp reduce ----
            float nq = s0 * s0 + s1 * s1;
#pragma unroll
            for (int off = 16; off > 0; off >>= 1)
                nq += __shfl_xor_sync(FULLMASK, nq, off);
            const float rn    = frsq(nq + 1e-20f);
            const float nrm   = nq * rn;                       // sqrt(nq)
            const float scale = nq * frcp((1.0f + nq) * (nrm + 1e-8f));

            if (it == 2) {   // ---- final: write v ----
                *reinterpret_cast<float2*>(out + (size_t)b * 64 + 2 * l) =
                    make_float2(s0 * scale, s1 * scale);
                break;
            }

            // ---- agreement: butterfly reduce-scatter over 64 rows ----
            float red[32];
            {
                const bool hi = l & 1;
#pragma unroll
                for (int i = 0; i < 32; i++) {
                    float t0 = fmaf(xc[i].y,      s1, xc[i].x      * s0);
                    float t1 = fmaf(xc[i + 32].y, s1, xc[i + 32].x * s0);
                    float send = hi ? t0 : t1;
                    float recv = __shfl_xor_sync(FULLMASK, send, 1);
                    red[i] = (hi ? t1 : t0) + recv;
                }
            }
#pragma unroll
            for (int k = 1; k < 5; k++) {
                const int half = 32 >> k;
                const bool hi = (l >> k) & 1;
#pragma unroll
                for (int i = 0; i < half; i++) {
                    float send = hi ? red[i] : red[i + half];
                    float recv = __shfl_xor_sync(FULLMASK, send, 1 << k);
                    red[i] = (hi ? red[i + half] : red[i]) + recv;
                }
            }
            // red[0] -> row r0, red[1] -> row r0+1 (scale folded post-reduce)
            blog0 += red[0] * scale;
            blog1 += red[1] * scale;
            e0 = __expf(blog0);
            e1 = __expf(blog1);
            __syncwarp();              // all lanes' se reads (s-phase) done
            *reinterpret_cast<float2*>(&sew[r0]) = make_float2(e0, e1);
            __syncwarp();              // se visible for next s-phase
        }
    }
}

extern "C" void kernel_launch(void* const* d_in, const int* in_sizes, int n_in,
                              void* d_out, int out_size)
{
    const float* x = (const float*)d_in[0];
    float* out = (float*)d_out;
    const int B = in_sizes[0] / 4096;
    int grid = 148 * 3;                // persistent: 3 CTAs/SM, 12 warps/SM
    if (grid * 4 > B) grid = (B + 3) / 4;
    routing_kernel<<<grid, 128>>>(x, out, B);
}